// round 1
// baseline (speedup 1.0000x reference)
#include <cuda_runtime.h>
#include <math.h>

#define LEVEL 16

// Global accumulator for the reduction (double for numerical safety vs
// the reference's fp32 tree reduction). Re-zeroed every launch by
// init_kernel so the launch sequence is deterministic under graph replay.
__device__ double g_sum;

__global__ void init_kernel() { g_sum = 0.0; }

// Pass 1: acc = sum_j | sum_t x[t, j] |   (vectorized over float4 lanes)
__global__ void reduce_kernel(const float4* __restrict__ x, int M4) {
    int tid = blockIdx.x * blockDim.x + threadIdx.x;
    int stride = gridDim.x * blockDim.x;

    float acc = 0.0f;
    for (int j = tid; j < M4; j += stride) {
        float sx = 0.f, sy = 0.f, sz = 0.f, sw = 0.f;
#pragma unroll
        for (int t = 0; t < LEVEL; t++) {
            float4 v = __ldcs(&x[(size_t)t * M4 + j]);
            sx += v.x; sy += v.y; sz += v.z; sw += v.w;
        }
        acc += fabsf(sx) + fabsf(sy) + fabsf(sz) + fabsf(sw);
    }

    // warp reduce
#pragma unroll
    for (int o = 16; o > 0; o >>= 1)
        acc += __shfl_down_sync(0xFFFFFFFFu, acc, o);

    __shared__ float warp_sums[32];
    int lane = threadIdx.x & 31;
    int wid  = threadIdx.x >> 5;
    if (lane == 0) warp_sums[wid] = acc;
    __syncthreads();

    if (wid == 0) {
        int nwarps = blockDim.x >> 5;
        acc = (lane < nwarps) ? warp_sums[lane] : 0.0f;
#pragma unroll
        for (int o = 16; o > 0; o >>= 1)
            acc += __shfl_down_sync(0xFFFFFFFFu, acc, o);
        if (lane == 0) atomicAdd(&g_sum, (double)acc);
    }
}

// One ST-BIF neuron step for a single scalar lane. Matches the reference
// exactly: pos = (v - v_th >= 0) && (T < 15); neg = (v < 0) && (T > 0);
// neg overrides pos.
__device__ __forceinline__ float bif_step(float& v, float& T, float xt, float v_th) {
    v += xt;
    float s = 0.0f;
    if (v - v_th >= 0.0f && T - 15.0f < 0.0f) s = 1.0f;
    if (v < 0.0f && T > 0.0f)                 s = -1.0f;
    v -= v_th * s;
    T += s;
    return s;
}

// Pass 2: 16-step serial scan per element; out[t,j] = spike * v_th.
__global__ void scan_kernel(const float4* __restrict__ x,
                            float4* __restrict__ out, int M4) {
    int j = blockIdx.x * blockDim.x + threadIdx.x;
    if (j >= M4) return;

    // v_th = mean(|col sums|) * 2 / sqrt(15)
    double mean = g_sum / (4.0 * (double)M4);
    float v_th = (float)(mean * 2.0 / sqrt(15.0));

    float vx = 0.5f * v_th, vy = vx, vz = vx, vw = vx;
    float Tx = 0.f, Ty = 0.f, Tz = 0.f, Tw = 0.f;

#pragma unroll
    for (int t = 0; t < LEVEL; t++) {
        float4 xt = __ldcs(&x[(size_t)t * M4 + j]);
        float4 o;
        o.x = bif_step(vx, Tx, xt.x, v_th) * v_th;
        o.y = bif_step(vy, Ty, xt.y, v_th) * v_th;
        o.z = bif_step(vz, Tz, xt.z, v_th) * v_th;
        o.w = bif_step(vw, Tw, xt.w, v_th) * v_th;
        __stcs(&out[(size_t)t * M4 + j], o);
    }
}

extern "C" void kernel_launch(void* const* d_in, const int* in_sizes, int n_in,
                              void* d_out, int out_size) {
    const float4* x = (const float4*)d_in[0];
    float4* out = (float4*)d_out;

    int n_total = in_sizes[0];            // 32*2048*1024 = 67,108,864
    int M4 = n_total / LEVEL / 4;          // 1,048,576 float4 columns

    init_kernel<<<1, 1>>>();
    reduce_kernel<<<2048, 256>>>(x, M4);
    scan_kernel<<<(M4 + 255) / 256, 256>>>(x, out, M4);
}

// round 2
// speedup vs baseline: 1.0443x; 1.0443x over previous
#include <cuda_runtime.h>
#include <math.h>

#define LEVEL 16
#define NBLK_R 1024           // reduce blocks (also partials count)
#define TPB 256

// Per-block partial sums from the reduce pass. Every slot is overwritten
// deterministically on every launch — no init kernel, no atomics.
__device__ double g_partials[NBLK_R];

// ---------------------------------------------------------------------------
// Pass 1: partials[b] = sum over this block's j of | sum_t x[t, j] |
// Forward grid-stride order + __ldcg so the tail of the input remains
// L2-resident for the scan pass (L2 survives kernel boundaries on sm_103a).
// ---------------------------------------------------------------------------
__global__ void reduce_kernel(const float4* __restrict__ x, int M4) {
    int tid = blockIdx.x * blockDim.x + threadIdx.x;
    int stride = gridDim.x * blockDim.x;

    float acc = 0.0f;
    for (int j = tid; j < M4; j += stride) {
        float sx = 0.f, sy = 0.f, sz = 0.f, sw = 0.f;
#pragma unroll
        for (int t = 0; t < LEVEL; t++) {
            float4 v = __ldcg(&x[(size_t)t * M4 + j]);
            sx += v.x; sy += v.y; sz += v.z; sw += v.w;
        }
        acc += fabsf(sx) + fabsf(sy) + fabsf(sz) + fabsf(sw);
    }

#pragma unroll
    for (int o = 16; o > 0; o >>= 1)
        acc += __shfl_down_sync(0xFFFFFFFFu, acc, o);

    __shared__ float warp_sums[TPB / 32];
    int lane = threadIdx.x & 31;
    int wid  = threadIdx.x >> 5;
    if (lane == 0) warp_sums[wid] = acc;
    __syncthreads();

    if (wid == 0) {
        acc = (lane < TPB / 32) ? warp_sums[lane] : 0.0f;
#pragma unroll
        for (int o = 16; o > 0; o >>= 1)
            acc += __shfl_down_sync(0xFFFFFFFFu, acc, o);
        if (lane == 0) g_partials[blockIdx.x] = (double)acc;
    }
}

// One ST-BIF neuron step (matches reference: neg overrides pos).
__device__ __forceinline__ float bif_step(float& v, float& T, float xt, float v_th) {
    v += xt;
    float s = 0.0f;
    if (v - v_th >= 0.0f && T - 15.0f < 0.0f) s = 1.0f;
    if (v < 0.0f && T > 0.0f)                 s = -1.0f;
    v -= v_th * s;
    T += s;
    return s;
}

// ---------------------------------------------------------------------------
// Pass 2: per-column 16-step scan. Blocks mapped in REVERSE j order so the
// first waves hit the input tail that pass 1 left resident in L2.
// __ldcs/__stcs (evict-first) keep this pass's own traffic from polluting L2.
// ---------------------------------------------------------------------------
__global__ void scan_kernel(const float4* __restrict__ x,
                            float4* __restrict__ out, int M4) {
    // Preamble: warp 0 sums the 1024 partials (8 KB, L2-hit), computes v_th.
    __shared__ float s_vth;
    if (threadIdx.x < 32) {
        double d = 0.0;
#pragma unroll
        for (int i = threadIdx.x; i < NBLK_R; i += 32)
            d += g_partials[i];
#pragma unroll
        for (int o = 16; o > 0; o >>= 1)
            d += __shfl_down_sync(0xFFFFFFFFu, d, o);
        if (threadIdx.x == 0) {
            double mean = d / (4.0 * (double)M4);
            s_vth = (float)(mean * 2.0 / sqrt(15.0));
        }
    }
    __syncthreads();
    float v_th = s_vth;

    // Reverse block mapping: block 0 handles the highest j range.
    int jblk = gridDim.x - 1 - blockIdx.x;
    int j = jblk * TPB + threadIdx.x;
    if (j >= M4) return;

    float vx = 0.5f * v_th, vy = vx, vz = vx, vw = vx;
    float Tx = 0.f, Ty = 0.f, Tz = 0.f, Tw = 0.f;

#pragma unroll
    for (int t = 0; t < LEVEL; t++) {
        float4 xt = __ldcs(&x[(size_t)t * M4 + j]);
        float4 o;
        o.x = bif_step(vx, Tx, xt.x, v_th) * v_th;
        o.y = bif_step(vy, Ty, xt.y, v_th) * v_th;
        o.z = bif_step(vz, Tz, xt.z, v_th) * v_th;
        o.w = bif_step(vw, Tw, xt.w, v_th) * v_th;
        __stcs(&out[(size_t)t * M4 + j], o);
    }
}

extern "C" void kernel_launch(void* const* d_in, const int* in_sizes, int n_in,
                              void* d_out, int out_size) {
    const float4* x = (const float4*)d_in[0];
    float4* out = (float4*)d_out;

    int n_total = in_sizes[0];         // 32*2048*1024
    int M4 = n_total / LEVEL / 4;      // 1,048,576 float4 columns

    reduce_kernel<<<NBLK_R, TPB>>>(x, M4);
    scan_kernel<<<(M4 + TPB - 1) / TPB, TPB>>>(x, out, M4);
}

// round 3
// speedup vs baseline: 1.0811x; 1.0353x over previous
#include <cuda_runtime.h>
#include <math.h>

#define LEVEL 16
#define NBLK_R 1024           // reduce blocks (also partials count)
#define TPB 256

// Per-block partial sums from the reduce pass. Every slot is overwritten
// deterministically on every launch — no init kernel, no atomics.
__device__ double g_partials[NBLK_R];

// ---------------------------------------------------------------------------
// Pass 1: partials[b] = sum over this block's j of | sum_t x[t, j] |
// Forward order + __ldcg so the tail of the input remains L2-resident for
// the scan pass (L2 survives kernel boundaries on sm_103a).
// ---------------------------------------------------------------------------
__global__ void reduce_kernel(const float4* __restrict__ x, int M4) {
    int tid = blockIdx.x * blockDim.x + threadIdx.x;
    int stride = gridDim.x * blockDim.x;

    float acc = 0.0f;
    for (int j = tid; j < M4; j += stride) {
        float sx = 0.f, sy = 0.f, sz = 0.f, sw = 0.f;
#pragma unroll
        for (int t = 0; t < LEVEL; t++) {
            float4 v = __ldcg(&x[(size_t)t * M4 + j]);
            sx += v.x; sy += v.y; sz += v.z; sw += v.w;
        }
        acc += fabsf(sx) + fabsf(sy) + fabsf(sz) + fabsf(sw);
    }

#pragma unroll
    for (int o = 16; o > 0; o >>= 1)
        acc += __shfl_down_sync(0xFFFFFFFFu, acc, o);

    __shared__ float warp_sums[TPB / 32];
    int lane = threadIdx.x & 31;
    int wid  = threadIdx.x >> 5;
    if (lane == 0) warp_sums[wid] = acc;
    __syncthreads();

    if (wid == 0) {
        acc = (lane < TPB / 32) ? warp_sums[lane] : 0.0f;
#pragma unroll
        for (int o = 16; o > 0; o >>= 1)
            acc += __shfl_down_sync(0xFFFFFFFFu, acc, o);
        if (lane == 0) g_partials[blockIdx.x] = (double)acc;
    }
}

// One ST-BIF neuron step (matches reference: neg overrides pos).
__device__ __forceinline__ float bif_step(float& v, float& T, float xt, float v_th) {
    v += xt;
    float s = 0.0f;
    if (v - v_th >= 0.0f && T - 15.0f < 0.0f) s = 1.0f;
    if (v < 0.0f && T > 0.0f)                 s = -1.0f;
    v -= v_th * s;
    T += s;
    return s;
}

// ---------------------------------------------------------------------------
// Pass 2: per-column 16-step scan with ALL 16 loads batched up front
// (MLP_p1 = 16) so the L1tex queue stays full against DRAM latency.
// Reverse j order to hit the L2 residue from pass 1; __ldcs/__stcs keep this
// pass's own traffic evict-first.
// ---------------------------------------------------------------------------
__global__ void __launch_bounds__(TPB) scan_kernel(const float4* __restrict__ x,
                                                   float4* __restrict__ out, int M4) {
    // Preamble: warp 0 sums the 1024 partials (8 KB, L2-hot), computes v_th.
    __shared__ float s_vth;
    if (threadIdx.x < 32) {
        double d = 0.0;
#pragma unroll
        for (int i = threadIdx.x; i < NBLK_R; i += 32)
            d += g_partials[i];
#pragma unroll
        for (int o = 16; o > 0; o >>= 1)
            d += __shfl_down_sync(0xFFFFFFFFu, d, o);
        if (threadIdx.x == 0) {
            double mean = d / (4.0 * (double)M4);
            s_vth = (float)(mean * 2.0 / sqrt(15.0));
        }
    }
    __syncthreads();
    float v_th = s_vth;

    // Reverse block mapping: block 0 handles the highest j range.
    int jblk = gridDim.x - 1 - blockIdx.x;
    int j = jblk * TPB + threadIdx.x;
    if (j >= M4) return;

    // Burst-read all 16 time steps (64 regs of data in flight).
    float4 r[LEVEL];
#pragma unroll
    for (int t = 0; t < LEVEL; t++)
        r[t] = __ldcs(&x[(size_t)t * M4 + j]);

    float vx = 0.5f * v_th, vy = vx, vz = vx, vw = vx;
    float Tx = 0.f, Ty = 0.f, Tz = 0.f, Tw = 0.f;

#pragma unroll
    for (int t = 0; t < LEVEL; t++) {
        float4 o;
        o.x = bif_step(vx, Tx, r[t].x, v_th) * v_th;
        o.y = bif_step(vy, Ty, r[t].y, v_th) * v_th;
        o.z = bif_step(vz, Tz, r[t].z, v_th) * v_th;
        o.w = bif_step(vw, Tw, r[t].w, v_th) * v_th;
        __stcs(&out[(size_t)t * M4 + j], o);
    }
}

extern "C" void kernel_launch(void* const* d_in, const int* in_sizes, int n_in,
                              void* d_out, int out_size) {
    const float4* x = (const float4*)d_in[0];
    float4* out = (float4*)d_out;

    int n_total = in_sizes[0];         // 32*2048*1024
    int M4 = n_total / LEVEL / 4;      // 1,048,576 float4 columns

    reduce_kernel<<<NBLK_R, TPB>>>(x, M4);
    scan_kernel<<<(M4 + TPB - 1) / TPB, TPB>>>(x, out, M4);
}